// round 2
// baseline (speedup 1.0000x reference)
#include <cuda_runtime.h>
#include <math.h>

namespace {
constexpr int Himg = 512, Wimg = 512, Bimg = 32;
constexpr int TILE_W = 64, TILE_H = 32, ROWS = 8;
constexpr int SWID = TILE_W + 2;   // 66
constexpr int SHGT = TILE_H + 2;   // 34
}

// 11 accumulators: [0]=mask sum, [1..4]=inp S1..S4, [5..8]=out S1..S4, [9]=tex, [10]=shape
__device__ double g_acc[11];

__global__ void zero_kernel() {
    int i = threadIdx.x;
    if (i < 11) g_acc[i] = 0.0;
}

#define WRED(v)                                      \
    v += __shfl_xor_sync(0xffffffffu, v, 16);        \
    v += __shfl_xor_sync(0xffffffffu, v, 8);         \
    v += __shfl_xor_sync(0xffffffffu, v, 4);         \
    v += __shfl_xor_sync(0xffffffffu, v, 2);         \
    v += __shfl_xor_sync(0xffffffffu, v, 1);

__global__ __launch_bounds__(256) void loss_kernel(
    const float* __restrict__ inp, const float* __restrict__ outp,
    const float* __restrict__ mask) {
    __shared__ float si[SHGT * SWID];
    __shared__ float so[SHGT * SWID];
    __shared__ double red[8][11];

    const int tx = threadIdx.x;         // 0..63
    const int ty = threadIdx.y;         // 0..3
    const int tid = ty * TILE_W + tx;
    const int img = blockIdx.z;
    const int x0 = blockIdx.x * TILE_W;
    const int y0 = blockIdx.y * TILE_H;
    const size_t ibase = (size_t)img * (size_t)(Himg * Wimg);

    // Cooperative halo load with zero padding (per-image boundaries)
    for (int idx = tid; idx < SHGT * SWID; idx += 256) {
        int r = idx / SWID;
        int c = idx - r * SWID;
        int gy = y0 + r - 1;
        int gx = x0 + c - 1;
        float vi = 0.f, vo = 0.f;
        if (gx >= 0 && gx < Wimg && gy >= 0 && gy < Himg) {
            size_t off = ibase + (size_t)gy * Wimg + (size_t)gx;
            vi = inp[off];
            vo = outp[off];
        }
        si[idx] = vi;
        so[idx] = vo;
    }
    __syncthreads();

    const int c = tx;                 // smem col: left=c, mid=c+1, right=c+2
    const int rbase = ty * ROWS;      // first output row (tile-local)

    // ---- prime rolling window (inp) ----
    // row0: only need rs/rq/mid; row1: full triple + rs/rq
    float t_l, t_m, t_r;
    int sr = rbase;                   // smem row index of window row0 (= output row - 1)
    t_l = si[sr * SWID + c]; t_m = si[sr * SWID + c + 1]; t_r = si[sr * SWID + c + 2];
    float irs0 = t_l + t_m + t_r;
    float irq0 = fmaf(t_l, t_l, fmaf(t_m, t_m, t_r * t_r));
    float im0 = t_m;
    sr = rbase + 1;
    float il1 = si[sr * SWID + c], im1 = si[sr * SWID + c + 1], ir1 = si[sr * SWID + c + 2];
    float irs1 = il1 + im1 + ir1;
    float irq1 = fmaf(il1, il1, fmaf(im1, im1, ir1 * ir1));

    // ---- prime rolling window (out) ----
    sr = rbase;
    t_l = so[sr * SWID + c]; t_m = so[sr * SWID + c + 1]; t_r = so[sr * SWID + c + 2];
    float ors0 = t_l + t_m + t_r;
    float orq0 = fmaf(t_l, t_l, fmaf(t_m, t_m, t_r * t_r));
    float om0 = t_m;
    sr = rbase + 1;
    float ol1 = so[sr * SWID + c], om1 = so[sr * SWID + c + 1], or1 = so[sr * SWID + c + 2];
    float ors1 = ol1 + om1 + or1;
    float orq1 = fmaf(ol1, ol1, fmaf(om1, om1, or1 * or1));

    // per-thread accumulators (8 samples each -> float is plenty)
    float a0 = 0.f;
    float ai1 = 0.f, ai2 = 0.f, ai3 = 0.f, ai4 = 0.f;
    float ao1 = 0.f, ao2 = 0.f, ao3 = 0.f, ao4 = 0.f;
    float atex = 0.f, ashp = 0.f;

    const float* mrow = mask + ibase + (size_t)(y0 + rbase) * Wimg + (size_t)(x0 + c);
    const float C9 = 1.f / 9.f;

#pragma unroll
    for (int k = 0; k < ROWS; k++) {
        int sr2 = rbase + k + 2;
        // new bottom rows
        float il2 = si[sr2 * SWID + c], im2 = si[sr2 * SWID + c + 1], ir2 = si[sr2 * SWID + c + 2];
        float ol2 = so[sr2 * SWID + c], om2 = so[sr2 * SWID + c + 1], or2 = so[sr2 * SWID + c + 2];
        float irs2 = il2 + im2 + ir2;
        float irq2 = fmaf(il2, il2, fmaf(im2, im2, ir2 * ir2));
        float ors2 = ol2 + om2 + or2;
        float orq2 = fmaf(ol2, ol2, fmaf(om2, om2, or2 * or2));

        // stencil quantities for output row rbase+k
        float is1 = irs0 + irs1 + irs2;
        float is2 = irq0 + irq1 + irq2;
        float os1 = ors0 + ors1 + ors2;
        float os2 = orq0 + orq1 + orq2;

        float lap_i = im0 + im2 + il1 + ir1 - 4.f * im1;
        float lap_o = om0 + om2 + ol1 + or1 - 4.f * om1;

        float mean_i = is1 * C9;
        float lv_i = fmaf(-mean_i, mean_i, is2 * C9);
        float mean_o = os1 * C9;
        float lv_o = fmaf(-mean_o, mean_o, os2 * C9);

        float ci = im1;   // center input value
        float co = om1;   // center output value
        float mk = mrow[k * Wimg];

        a0 += mk;
        float t = ci * mk; ai1 += t; t *= ci; ai2 += t; t *= ci; ai3 += t; t *= ci; ai4 += t;
        float u = co * mk; ao1 += u; u *= co; ao2 += u; u *= co; ao3 += u; u *= co; ao4 += u;
        atex += fabsf(lv_o - lv_i) * mk;
        ashp += fabsf(lap_o - lap_i) * mk;

        // roll windows down
        irs0 = irs1; irq0 = irq1; im0 = im1;
        il1 = il2; im1 = im2; ir1 = ir2; irs1 = irs2; irq1 = irq2;
        ors0 = ors1; orq0 = orq1; om0 = om1;
        ol1 = ol2; om1 = om2; or1 = or2; ors1 = ors2; orq1 = orq2;
    }

    // ---- reduction: warp shuffle (float), then cross-warp in double ----
    WRED(a0);
    WRED(ai1); WRED(ai2); WRED(ai3); WRED(ai4);
    WRED(ao1); WRED(ao2); WRED(ao3); WRED(ao4);
    WRED(atex); WRED(ashp);

    int warp = tid >> 5, lane = tid & 31;
    if (lane == 0) {
        red[warp][0] = (double)a0;
        red[warp][1] = (double)ai1; red[warp][2] = (double)ai2;
        red[warp][3] = (double)ai3; red[warp][4] = (double)ai4;
        red[warp][5] = (double)ao1; red[warp][6] = (double)ao2;
        red[warp][7] = (double)ao3; red[warp][8] = (double)ao4;
        red[warp][9] = (double)atex; red[warp][10] = (double)ashp;
    }
    __syncthreads();
    if (tid < 11) {
        double s = 0.0;
#pragma unroll
        for (int w = 0; w < 8; w++) s += red[w][tid];
        atomicAdd(&g_acc[tid], s);
    }
}

__global__ void finalize_kernel(float* out) {
    if (threadIdx.x != 0 || blockIdx.x != 0) return;
    const double EPS = 1e-8;
    double S0 = g_acc[0];
    double A1 = g_acc[1], A2 = g_acc[2], A3 = g_acc[3], A4 = g_acc[4];
    double B1 = g_acc[5], B2 = g_acc[6], B3 = g_acc[7], B4 = g_acc[8];
    double TXs = g_acc[9], SHs = g_acc[10];

    double ms = S0 + EPS;
    double im = A1 / ms, om = B1 / ms;

    // central moment sums via binomial expansion of raw moments
    double im2 = im * im, im3 = im2 * im, im4 = im2 * im2;
    double om2 = om * om, om3 = om2 * om, om4 = om2 * om2;

    double di2 = A2 - 2.0 * im * A1 + im2 * S0;
    double di3 = A3 - 3.0 * im * A2 + 3.0 * im2 * A1 - im3 * S0;
    double di4 = A4 - 4.0 * im * A3 + 6.0 * im2 * A2 - 4.0 * im3 * A1 + im4 * S0;
    double do2 = B2 - 2.0 * om * B1 + om2 * S0;
    double do3 = B3 - 3.0 * om * B2 + 3.0 * om2 * B1 - om3 * S0;
    double do4 = B4 - 4.0 * om * B3 + 6.0 * om2 * B2 - 4.0 * om3 * B1 + om4 * S0;

    double iv = di2 / ms, ov = do2 / ms;
    double isk = di3 / (ms * (iv * sqrt(iv) + EPS));
    double osk = do3 / (ms * (ov * sqrt(ov) + EPS));
    double iku = di4 / (ms * (iv * iv + EPS));
    double oku = do4 / (ms * (ov * ov + EPS));

    double dm = im - om, dv = iv - ov, dsk = isk - osk, dku = iku - oku;
    double intensity = dm * dm + dv * dv + dsk * dsk + dku * dku;

    const double NTOT = (double)Bimg * (double)Himg * (double)Wimg; // 8388608
    double texture = TXs / NTOT;
    double shapev = SHs / NTOT;
    double total = 1.0 * intensity + 1.0 * texture + 0.5 * shapev;

    out[0] = (float)intensity;
    out[1] = (float)texture;
    out[2] = (float)shapev;
    out[3] = (float)total;
}

extern "C" void kernel_launch(void* const* d_in, const int* in_sizes, int n_in,
                              void* d_out, int out_size) {
    (void)in_sizes; (void)n_in; (void)out_size;
    const float* inp  = (const float*)d_in[0];
    const float* outp = (const float*)d_in[1];
    const float* mask = (const float*)d_in[2];

    zero_kernel<<<1, 32>>>();
    dim3 grid(Wimg / TILE_W, Himg / TILE_H, Bimg);   // 8 x 16 x 32
    dim3 block(TILE_W, TILE_H / ROWS);               // 64 x 4 = 256
    loss_kernel<<<grid, block>>>(inp, outp, mask);
    finalize_kernel<<<1, 1>>>((float*)d_out);
}